// round 8
// baseline (speedup 1.0000x reference)
#include <cuda_runtime.h>
#include <cuda_fp16.h>
#include <cstdint>

#define M_DIM 4096
#define K_DIM 4096
#define B_DIM 4
#define N_DIM 2048
#define BN_DIM (B_DIM * N_DIM)      // 8192

// GEMM tiling: CTA 128x128, 4 warps of 64x64, BK=64
#define BM 128
#define BN 128
#define BK 64                        // fp16 elems per k-tile (4 k16 steps)
#define NSTAGE 3
#define PADK 72                      // pitch in halves (144 B): conflict-free ldmatrix
#define TRB (PADK * 2)               // tile row bytes = 144
#define A_TILE_BYTES (BM * TRB)      // 18432
#define B_TILE_BYTES (BN * TRB)      // 18432
#define STAGE_BYTES (A_TILE_BYTES + B_TILE_BYTES)   // 36864
#define SMEM_TOTAL (NSTAGE * STAGE_BYTES)           // 110592 -> 2 CTAs/SM
#define NKT (K_DIM / BK)             // 64

// ---------------- scratch ----------------------------------------------------
__device__ __align__(1024) __half g_Wh[(size_t)M_DIM * K_DIM];
__device__ __align__(1024) __half g_Xh[(size_t)BN_DIM * K_DIM];

// ---------------- helpers ----------------------------------------------------
__device__ __forceinline__ uint32_t smem_u32(const void* p) {
    uint32_t a;
    asm("{ .reg .u64 t; cvta.to.shared.u64 t, %1; cvt.u32.u64 %0, t; }" : "=r"(a) : "l"(p));
    return a;
}

#define CP16(dst_u32, src_ptr) \
    asm volatile("cp.async.cg.shared.global [%0], [%1], 16;" \
                 :: "r"(dst_u32), "l"(src_ptr) : "memory")
#define CP_COMMIT() asm volatile("cp.async.commit_group;" ::: "memory")
#define CP_WAIT(n)  asm volatile("cp.async.wait_group %0;" :: "n"(n) : "memory")

__device__ __forceinline__ void ldsm_x4(uint32_t* r, uint32_t addr) {
    asm volatile("ldmatrix.sync.aligned.m8n8.x4.shared.b16 {%0,%1,%2,%3}, [%4];"
        : "=r"(r[0]), "=r"(r[1]), "=r"(r[2]), "=r"(r[3]) : "r"(addr));
}

// f16 accumulator MMA, C = 0 (chunk start)
__device__ __forceinline__ void mma16816_h_z(uint32_t* d, const uint32_t* a,
                                             const uint32_t* b) {
    asm volatile(
        "mma.sync.aligned.m16n8k16.row.col.f16.f16.f16.f16 "
        "{%0,%1}, {%2,%3,%4,%5}, {%6,%7}, {%8,%8};"
        : "=r"(d[0]), "=r"(d[1])
        : "r"(a[0]), "r"(a[1]), "r"(a[2]), "r"(a[3]),
          "r"(b[0]), "r"(b[1]), "r"(0u));
}

// f16 accumulator MMA, C = D (chain)
__device__ __forceinline__ void mma16816_h(uint32_t* d, const uint32_t* a,
                                           const uint32_t* b) {
    asm volatile(
        "mma.sync.aligned.m16n8k16.row.col.f16.f16.f16.f16 "
        "{%0,%1}, {%2,%3,%4,%5}, {%6,%7}, {%0,%1};"
        : "+r"(d[0]), "+r"(d[1])
        : "r"(a[0]), "r"(a[1]), "r"(a[2]), "r"(a[3]),
          "r"(b[0]), "r"(b[1]));
}

// ---------------- prep kernels -----------------------------------------------
__global__ void __launch_bounds__(256) zero_wh_kernel() {
    size_t i = ((size_t)blockIdx.x * 256 + threadIdx.x) * 8;   // 8 halves = 16 B
    if (i < (size_t)M_DIM * K_DIM)
        *reinterpret_cast<float4*>(&g_Wh[i]) = make_float4(0.f, 0.f, 0.f, 0.f);
}

// Deterministic CSR scatter straight to fp16: fold duplicate runs in fp32.
__global__ void __launch_bounds__(128) scatter_kernel(
    const float* __restrict__ values, const int* __restrict__ row_offsets,
    const int* __restrict__ cols) {
    const int m = blockIdx.x;
    const int s = row_offsets[m], e = row_offsets[m + 1];
    for (int j = s + threadIdx.x; j < e; j += 128) {
        const int c = cols[j];
        if (j > s && cols[j - 1] == c) continue;
        float sum = values[j];
        int jj = j + 1;
        while (jj < e && cols[jj] == c) { sum += values[jj]; jj++; }
        g_Wh[(size_t)m * K_DIM + c] = __float2half_rn(sum);
    }
}

__global__ void __launch_bounds__(256) convx_kernel(const float* __restrict__ x) {
    size_t i = ((size_t)blockIdx.x * 256 + threadIdx.x) * 4;
    if (i >= (size_t)BN_DIM * K_DIM) return;
    float4 w = *reinterpret_cast<const float4*>(&x[i]);
    *reinterpret_cast<__half2*>(&g_Xh[i]) =
        __halves2half2(__float2half_rn(w.x), __float2half_rn(w.y));
    *reinterpret_cast<__half2*>(&g_Xh[i + 2]) =
        __halves2half2(__float2half_rn(w.z), __float2half_rn(w.w));
}

// ---------------- GEMM -------------------------------------------------------
// C[M, BN_DIM] = Wh * Xh^T.  f16 accumulation over K=32 chunks, promoted to
// f32 per chunk.  128 threads, warp grid 2x2, warp tile 64x64.  2 CTAs/SM.
__global__ void __launch_bounds__(128, 2) gemm_kernel(float* __restrict__ out) {
    extern __shared__ char smem[];
    const int tid  = threadIdx.x;
    const int wid  = tid >> 5;
    const int lane = tid & 31;
    const int grp  = lane >> 2;
    const int tig  = lane & 3;
    const int wm0  = (wid & 1) * 64;
    const int wn0  = (wid >> 1) * 64;
    const int m0   = blockIdx.x * BM;
    const int bn0  = blockIdx.y * BN;

    const uint32_t sbase = smem_u32(smem);

    // ldmatrix lane-derived address components
    const int a_row_l = (lane & 7) + 8 * ((lane >> 3) & 1);
    const int a_kx    = 16 * ((lane >> 4) & 1);
    const int b_row_l = (lane & 7) + 8 * ((lane >> 4) & 1);
    const int b_kx    = 16 * ((lane >> 3) & 1);

    const __half* gA = g_Wh + (size_t)m0  * K_DIM;
    const __half* gB = g_Xh + (size_t)bn0 * K_DIM;

    // cp.async per stage: 1024 chunks A + 1024 chunks B (16 B each), 128 thr
    #define LOAD_STAGE(stg, ktidx) do {                                         \
        const uint32_t sb_ = sbase + (stg) * STAGE_BYTES;                       \
        const int kh_ = (ktidx) * BK;                                           \
        _Pragma("unroll")                                                       \
        for (int i_ = 0; i_ < 8; i_++) {                                        \
            const int c_   = tid + i_ * 128;                                    \
            const int row_ = c_ >> 3, ch_ = c_ & 7;                             \
            const uint32_t d_ = sb_ + row_ * TRB + ch_ * 16;                    \
            const size_t  g_  = (size_t)row_ * K_DIM + kh_ + ch_ * 8;           \
            CP16(d_, gA + g_);                                                  \
            CP16(d_ + A_TILE_BYTES, gB + g_);                                   \
        }                                                                       \
    } while (0)

    #pragma unroll
    for (int s = 0; s < NSTAGE - 1; s++) { LOAD_STAGE(s, s); CP_COMMIT(); }

    float acc[4][8][4];
    #pragma unroll
    for (int mt = 0; mt < 4; mt++)
        #pragma unroll
        for (int nt = 0; nt < 8; nt++)
            #pragma unroll
            for (int r = 0; r < 4; r++) acc[mt][nt][r] = 0.f;

    for (int kt = 0; kt < NKT; kt++) {
        CP_WAIT(NSTAGE - 2);
        __syncthreads();
        if (kt + NSTAGE - 1 < NKT) LOAD_STAGE((kt + NSTAGE - 1) % NSTAGE, kt + NSTAGE - 1);
        CP_COMMIT();

        const uint32_t st = sbase + (kt % NSTAGE) * STAGE_BYTES;
        const uint32_t sA = st;
        const uint32_t sB = st + A_TILE_BYTES;

        #pragma unroll
        for (int kp = 0; kp < 2; kp++) {          // two K=32 chunks per kt
            // B fragments for both k16 steps of this chunk
            uint32_t bf[2][8][2];
            #pragma unroll
            for (int s2 = 0; s2 < 2; s2++) {
                const int kb = (2 * kp + s2) * 32;
                #pragma unroll
                for (int ntp = 0; ntp < 4; ntp++) {
                    uint32_t r[4];
                    ldsm_x4(r, sB + (wn0 + 16 * ntp + b_row_l) * TRB + kb + b_kx);
                    bf[s2][2 * ntp][0]     = r[0];
                    bf[s2][2 * ntp][1]     = r[1];
                    bf[s2][2 * ntp + 1][0] = r[2];
                    bf[s2][2 * ntp + 1][1] = r[3];
                }
            }
            #pragma unroll
            for (int mt = 0; mt < 4; mt++) {
                uint32_t ah0[4], ah1[4];
                ldsm_x4(ah0, sA + (wm0 + 16 * mt + a_row_l) * TRB + (2 * kp) * 32 + a_kx);
                ldsm_x4(ah1, sA + (wm0 + 16 * mt + a_row_l) * TRB + (2 * kp + 1) * 32 + a_kx);
                uint32_t cc[8][2];
                #pragma unroll
                for (int nt = 0; nt < 8; nt++) mma16816_h_z(cc[nt], ah0, bf[0][nt]);
                #pragma unroll
                for (int nt = 0; nt < 8; nt++) mma16816_h(cc[nt], ah1, bf[1][nt]);
                // promote chunk result to f32 accumulators
                #pragma unroll
                for (int nt = 0; nt < 8; nt++) {
                    const __half2 h01 = *reinterpret_cast<const __half2*>(&cc[nt][0]);
                    const __half2 h23 = *reinterpret_cast<const __half2*>(&cc[nt][1]);
                    const float2 f01 = __half22float2(h01);
                    const float2 f23 = __half22float2(h23);
                    acc[mt][nt][0] += f01.x;
                    acc[mt][nt][1] += f01.y;
                    acc[mt][nt][2] += f23.x;
                    acc[mt][nt][3] += f23.y;
                }
            }
        }
    }

    // epilogue
    const int b  = bn0 >> 11;               // / N_DIM
    const int nb = bn0 & (N_DIM - 1);
    float* ob = out + (size_t)b * M_DIM * N_DIM;
    #pragma unroll
    for (int mt = 0; mt < 4; mt++) {
        const int row = m0 + wm0 + 16 * mt + grp;
        #pragma unroll
        for (int nt = 0; nt < 8; nt++) {
            const int col = nb + wn0 + 8 * nt + 2 * tig;
            *reinterpret_cast<float2*>(ob + (size_t)row * N_DIM + col) =
                make_float2(acc[mt][nt][0], acc[mt][nt][1]);
            *reinterpret_cast<float2*>(ob + (size_t)(row + 8) * N_DIM + col) =
                make_float2(acc[mt][nt][2], acc[mt][nt][3]);
        }
    }
}

// ---------------- host side --------------------------------------------------
extern "C" void kernel_launch(void* const* d_in, const int* in_sizes, int n_in,
                              void* d_out, int out_size) {
    const float* x           = (const float*)d_in[0];  // [B, N, K] == [BN, K]
    const float* values      = (const float*)d_in[1];
    const int*   row_offsets = (const int*)  d_in[2];
    const int*   col_indices = (const int*)  d_in[3];
    float*       out         = (float*)d_out;
    (void)in_sizes; (void)n_in; (void)out_size;

    const size_t wN = (size_t)M_DIM * K_DIM;
    const size_t xN = (size_t)BN_DIM * K_DIM;

    zero_wh_kernel<<<(unsigned)((wN / 8 + 255) / 256), 256>>>();
    scatter_kernel<<<M_DIM, 128>>>(values, row_offsets, col_indices);
    convx_kernel<<<(unsigned)((xN / 4 + 255) / 256), 256>>>(x);

    cudaFuncSetAttribute(gemm_kernel,
                         cudaFuncAttributeMaxDynamicSharedMemorySize, SMEM_TOTAL);
    gemm_kernel<<<dim3(M_DIM / BM, BN_DIM / BN), 128, SMEM_TOTAL>>>(out);
}

// round 10
// speedup vs baseline: 1.1237x; 1.1237x over previous
#include <cuda_runtime.h>
#include <cuda_fp16.h>
#include <cstdint>

#define M_DIM 4096
#define K_DIM 4096
#define B_DIM 4
#define N_DIM 2048
#define BN_DIM (B_DIM * N_DIM)      // 8192
#define KC_DIM (K_DIM / 2)          // compressed K = 2048
#define NK32 (K_DIM / 32)           // 128 metadata chunks per row
#define MT16 (M_DIM / 16)           // 256
#define RESCAP 128

// GEMM tiling: CTA 128x128, 4 warps of 64x64, dense BK=64 per stage
#define BM 128
#define BN 128
#define BK 64
#define NSTAGE 3
#define A_TRB 80                    // compressed A: 64B data, pitch 80 (CF ldmatrix)
#define B_TRB 144                   // dense B: 128B data, pitch 144
#define A_TILE (BM * A_TRB)         // 10240
#define B_TILE (BN * B_TRB)         // 18432
#define STAGE_BYTES (A_TILE + B_TILE)          // 28672
#define SMEM_TOTAL (NSTAGE * STAGE_BYTES)      // 86016 -> 2 CTAs/SM
#define NKT (K_DIM / BK)            // 64

// ---------------- scratch ----------------------------------------------------
__device__ __align__(1024) __half    g_Wh  [(size_t)M_DIM * K_DIM];    // dense fp16 W
__device__ __align__(1024) __half    g_Wc  [(size_t)M_DIM * KC_DIM];   // 2:4 compressed
__device__ __align__(1024) uint32_t  g_MetaT[(size_t)NK32 * M_DIM];    // per-row meta [k32][m]
__device__ __align__(1024) uint32_t  g_MetaP[(size_t)NK32 * MT16 * 16];// per-lane format
__device__ __align__(1024) __half    g_Xh  [(size_t)BN_DIM * K_DIM];   // X fp16 [bn][k]
__device__ __align__(1024) __half    g_XhT [(size_t)K_DIM * BN_DIM];   // X fp16 [k][bn]
__device__ int       g_ResCnt[M_DIM];
__device__ uint16_t  g_ResCol[(size_t)M_DIM * RESCAP];
__device__ float     g_ResVal[(size_t)M_DIM * RESCAP];

// ---------------- helpers ----------------------------------------------------
__device__ __forceinline__ uint32_t smem_u32(const void* p) {
    uint32_t a;
    asm("{ .reg .u64 t; cvta.to.shared.u64 t, %1; cvt.u32.u64 %0, t; }" : "=r"(a) : "l"(p));
    return a;
}

#define CP16(dst_u32, src_ptr) \
    asm volatile("cp.async.cg.shared.global [%0], [%1], 16;" \
                 :: "r"(dst_u32), "l"(src_ptr) : "memory")
#define CP_COMMIT() asm volatile("cp.async.commit_group;" ::: "memory")
#define CP_WAIT(n)  asm volatile("cp.async.wait_group %0;" :: "n"(n) : "memory")

__device__ __forceinline__ void ldsm_x4(uint32_t* r, uint32_t addr) {
    asm volatile("ldmatrix.sync.aligned.m8n8.x4.shared.b16 {%0,%1,%2,%3}, [%4];"
        : "=r"(r[0]), "=r"(r[1]), "=r"(r[2]), "=r"(r[3]) : "r"(addr));
}

// sparse 2:4 MMA: A compressed 16x16 (of 16x32), B dense 32x8, f32 acc
__device__ __forceinline__ void mmasp(float* d, const uint32_t* a,
                                      const uint32_t* b, uint32_t e) {
    asm volatile(
        "mma.sp::ordered_metadata.sync.aligned.m16n8k32.row.col.f32.f16.f16.f32 "
        "{%0,%1,%2,%3}, {%4,%5,%6,%7}, {%8,%9,%10,%11}, {%0,%1,%2,%3}, %12, 0x0;"
        : "+f"(d[0]), "+f"(d[1]), "+f"(d[2]), "+f"(d[3])
        : "r"(a[0]), "r"(a[1]), "r"(a[2]), "r"(a[3]),
          "r"(b[0]), "r"(b[1]), "r"(b[2]), "r"(b[3]), "r"(e));
}

// ---------------- prep kernels -----------------------------------------------
__global__ void __launch_bounds__(256) zero_wh_kernel() {
    size_t i = ((size_t)blockIdx.x * 256 + threadIdx.x) * 8;
    if (i < (size_t)M_DIM * K_DIM)
        *reinterpret_cast<float4*>(&g_Wh[i]) = make_float4(0.f, 0.f, 0.f, 0.f);
}

// Deterministic CSR scatter to fp16: fold duplicate runs in fp32.
__global__ void __launch_bounds__(128) scatter_kernel(
    const float* __restrict__ values, const int* __restrict__ row_offsets,
    const int* __restrict__ cols) {
    const int m = blockIdx.x;
    const int s = row_offsets[m], e = row_offsets[m + 1];
    for (int j = s + threadIdx.x; j < e; j += 128) {
        const int c = cols[j];
        if (j > s && cols[j - 1] == c) continue;
        float sum = values[j];
        int jj = j + 1;
        while (jj < e && cols[jj] == c) { sum += values[jj]; jj++; }
        g_Wh[(size_t)m * K_DIM + c] = __float2half_rn(sum);
    }
}

__global__ void __launch_bounds__(256) convx_kernel(const float* __restrict__ x) {
    size_t i = ((size_t)blockIdx.x * 256 + threadIdx.x) * 4;
    if (i >= (size_t)BN_DIM * K_DIM) return;
    float4 w = *reinterpret_cast<const float4*>(&x[i]);
    *reinterpret_cast<__half2*>(&g_Xh[i]) =
        __halves2half2(__float2half_rn(w.x), __float2half_rn(w.y));
    *reinterpret_cast<__half2*>(&g_Xh[i + 2]) =
        __halves2half2(__float2half_rn(w.z), __float2half_rn(w.w));
}

// x [bn][k] fp32 -> g_XhT [k][bn] fp16 (for the residual pass)
__global__ void __launch_bounds__(256) txp_kernel(const float* __restrict__ x) {
    __shared__ __half tile[32][33];
    const int bn0 = blockIdx.x * 32;
    const int k0  = blockIdx.y * 32;
    const int tx = threadIdx.x, ty = threadIdx.y;
    #pragma unroll
    for (int i = ty; i < 32; i += 8)
        tile[i][tx] = __float2half_rn(x[(size_t)(bn0 + i) * K_DIM + k0 + tx]);
    __syncthreads();
    #pragma unroll
    for (int i = ty; i < 32; i += 8)
        g_XhT[(size_t)(k0 + i) * BN_DIM + bn0 + tx] = tile[tx][i];
}

// 2:4 compression: warp per row.  Builds g_Wc, g_MetaT, residual lists.
__global__ void __launch_bounds__(32) compress_kernel() {
    const int m    = blockIdx.x;
    const int lane = threadIdx.x;
    const __half* wrow = g_Wh + (size_t)m * K_DIM;
    int base = 0;
    for (int rnd = 0; rnd < 4; rnd++) {
        const int c = rnd * 32 + lane;      // k32 chunk index 0..127
        uint32_t meta = 0;
        __half vals[16];
        uint16_t rescol[16];
        float    resval[16];
        int rcnt = 0;
        #pragma unroll
        for (int g = 0; g < 8; g++) {
            const int k0 = c * 32 + g * 4;
            __half h[4];
            int pos[4], np = 0;
            #pragma unroll
            for (int t = 0; t < 4; t++) {
                h[t] = wrow[k0 + t];
                if (__half_as_ushort(h[t]) != 0) pos[np++] = t;
            }
            int i0, i1; __half v0, v1;
            const __half hz = __ushort_as_half(0);
            if (np == 0)      { i0 = 0; i1 = 1; v0 = hz; v1 = hz; }
            else if (np == 1) {
                const int p = pos[0];
                if (p == 0) { i0 = 0; i1 = 1; v0 = h[0]; v1 = hz; }
                else        { i0 = 0; i1 = p; v0 = hz;   v1 = h[p]; }
            } else {
                i0 = pos[0]; i1 = pos[1]; v0 = h[i0]; v1 = h[i1];
                for (int e2 = 2; e2 < np; e2++) {
                    rescol[rcnt] = (uint16_t)(k0 + pos[e2]);
                    resval[rcnt] = __half2float(h[pos[e2]]);
                    rcnt++;
                }
            }
            vals[2 * g]     = v0;
            vals[2 * g + 1] = v1;
            meta |= (uint32_t)(i0 | (i1 << 2)) << (4 * g);
        }
        __half* dst = g_Wc + (size_t)m * KC_DIM + c * 16;
        #pragma unroll
        for (int t = 0; t < 8; t++)
            *reinterpret_cast<__half2*>(dst + 2 * t) =
                __halves2half2(vals[2 * t], vals[2 * t + 1]);
        g_MetaT[(size_t)c * M_DIM + m] = meta;
        // deterministic residual placement via warp scan
        int incl = rcnt;
        #pragma unroll
        for (int off = 1; off < 32; off <<= 1) {
            int o = __shfl_up_sync(0xffffffff, incl, off);
            if (lane >= off) incl += o;
        }
        const int total = __shfl_sync(0xffffffff, incl, 31);
        const int excl = incl - rcnt;
        for (int j = 0; j < rcnt; j++) {
            const int idx = base + excl + j;
            if (idx < RESCAP) {
                g_ResCol[(size_t)m * RESCAP + idx] = rescol[j];
                g_ResVal[(size_t)m * RESCAP + idx] = resval[j];
            }
        }
        base += total;
    }
    if (lane == 0) g_ResCnt[m] = base > RESCAP ? RESCAP : base;
}

// Repack per-row metadata into per-lane mma.sp format:
// word index ((c * MT16 + mtile) * 8 + quad) * 2 + pos
//   pos 0: bits[0:16] = meta(row, k0..15),  bits[16:32] = meta(row+8, k0..15)
//   pos 1: bits[0:16] = meta(row, k16..31), bits[16:32] = meta(row+8, k16..31)
// where row = mtile*16 + quad.
__global__ void __launch_bounds__(256) repack_meta_kernel() {
    const size_t i = (size_t)blockIdx.x * 256 + threadIdx.x;
    if (i >= (size_t)NK32 * MT16 * 16) return;
    const int pos   = (int)(i & 1);
    const int quad  = (int)((i >> 1) & 7);
    const int mtile = (int)((i >> 4) % MT16);
    const int c     = (int)(i / (16 * MT16));
    const int r0 = mtile * 16 + quad;
    const uint32_t w0 = g_MetaT[(size_t)c * M_DIM + r0];
    const uint32_t w1 = g_MetaT[(size_t)c * M_DIM + r0 + 8];
    uint32_t w;
    if (pos == 0) w = (w0 & 0xFFFFu) | (w1 << 16);
    else          w = (w0 >> 16) | (w1 & 0xFFFF0000u);
    g_MetaP[i] = w;
}

// ---------------- sparse GEMM ------------------------------------------------
// C[M, BN_DIM] = W24 * Xh^T.  128 threads, warp grid 2x2, warp tile 64x64.
__global__ void __launch_bounds__(128, 2) gemm_kernel(float* __restrict__ out) {
    extern __shared__ char smem[];
    const int tid  = threadIdx.x;
    const int wid  = tid >> 5;
    const int lane = tid & 31;
    const int grp  = lane >> 2;
    const int tig  = lane & 3;
    const int wm0  = (wid & 1) * 64;
    const int wn0  = (wid >> 1) * 64;
    const int m0   = blockIdx.x * BM;
    const int bn0  = blockIdx.y * BN;

    const uint32_t sbase = smem_u32(smem);

    const int a_row_l = (lane & 7) + 8 * ((lane >> 3) & 1);
    const int a_kx    = 16 * ((lane >> 4) & 1);
    const int b_row_l = (lane & 7) + 8 * ((lane >> 4) & 1);
    const int b_kx    = 16 * ((lane >> 3) & 1);
    // per-lane metadata word sub-index: quad*2 + pos (lanes 2,3 unused by HW)
    const int eidx    = (lane >> 2) * 2 + (lane & 1);
    const int mtile0  = (m0 + wm0) >> 4;

    const __half* gA = g_Wc + (size_t)m0  * KC_DIM;
    const __half* gB = g_Xh + (size_t)bn0 * K_DIM;

    // per stage: A 512 chunks (4/thr), B 1024 chunks (8/thr), 16B each
    #define LOAD_STAGE(stg, ktidx) do {                                         \
        const uint32_t sb_ = sbase + (stg) * STAGE_BYTES;                       \
        _Pragma("unroll")                                                       \
        for (int i_ = 0; i_ < 4; i_++) {                                        \
            const int c_ = tid + i_ * 128;                                      \
            const int row_ = c_ >> 2, ch_ = c_ & 3;                             \
            CP16(sb_ + row_ * A_TRB + ch_ * 16,                                 \
                 gA + (size_t)row_ * KC_DIM + (ktidx) * 32 + ch_ * 8);          \
        }                                                                       \
        _Pragma("unroll")                                                       \
        for (int i_ = 0; i_ < 8; i_++) {                                        \
            const int c_ = tid + i_ * 128;                                      \
            const int row_ = c_ >> 3, ch_ = c_ & 7;                             \
            CP16(sb_ + A_TILE + row_ * B_TRB + ch_ * 16,                        \
                 gB + (size_t)row_ * K_DIM + (ktidx) * BK + ch_ * 8);           \
        }                                                                       \
    } while (0)

    #pragma unroll
    for (int s = 0; s < NSTAGE - 1; s++) { LOAD_STAGE(s, s); CP_COMMIT(); }

    float acc[4][8][4];
    #pragma unroll
    for (int mt = 0; mt < 4; mt++)
        #pragma unroll
        for (int nt = 0; nt < 8; nt++)
            #pragma unroll
            for (int r = 0; r < 4; r++) acc[mt][nt][r] = 0.f;

    for (int kt = 0; kt < NKT; kt++) {
        // prefetch metadata for this kt (2 k32 chunks x 4 mt)
        uint32_t E[2][4];
        #pragma unroll
        for (int ch = 0; ch < 2; ch++)
            #pragma unroll
            for (int mt = 0; mt < 4; mt++)
                E[ch][mt] = __ldg(&g_MetaP[
                    ((size_t)(kt * 2 + ch) * MT16 + mtile0 + mt) * 16 + eidx]);

        CP_WAIT(NSTAGE - 2);
        __syncthreads();
        if (kt + NSTAGE - 1 < NKT) LOAD_STAGE((kt + NSTAGE - 1) % NSTAGE, kt + NSTAGE - 1);
        CP_COMMIT();

        const uint32_t st = sbase + (kt % NSTAGE) * STAGE_BYTES;
        const uint32_t sA = st;
        const uint32_t sB = st + A_TILE;

        #pragma unroll
        for (int ch = 0; ch < 2; ch++) {        // two dense-k32 chunks per kt
            const int kbB = ch * 64;            // B byte offset (32 halves)
            uint32_t bf[8][4];
            #pragma unroll
            for (int ntp = 0; ntp < 4; ntp++) {
                uint32_t lo[4], hi[4];
                const uint32_t baddr = sB + (wn0 + 16 * ntp + b_row_l) * B_TRB + b_kx;
                ldsm_x4(lo, baddr + kbB);
                ldsm_x4(hi, baddr + kbB + 32);
                bf[2 * ntp][0]     = lo[0]; bf[2 * ntp][1]     = lo[1];
                bf[2 * ntp][2]     = hi[0]; bf[2 * ntp][3]     = hi[1];
                bf[2 * ntp + 1][0] = lo[2]; bf[2 * ntp + 1][1] = lo[3];
                bf[2 * ntp + 1][2] = hi[2]; bf[2 * ntp + 1][3] = hi[3];
            }
            #pragma unroll
            for (int mt = 0; mt < 4; mt++) {
                uint32_t ah[4];
                ldsm_x4(ah, sA + (wm0 + 16 * mt + a_row_l) * A_TRB + ch * 32 + a_kx);
                #pragma unroll
                for (int nt = 0; nt < 8; nt++)
                    mmasp(acc[mt][nt], ah, bf[nt], E[ch][mt]);
            }
        }
    }

    const int b  = bn0 >> 11;
    const int nb = bn0 & (N_DIM - 1);
    float* ob = out + (size_t)b * M_DIM * N_DIM;
    #pragma unroll
    for (int mt = 0; mt < 4; mt++) {
        const int row = m0 + wm0 + 16 * mt + grp;
        #pragma unroll
        for (int nt = 0; nt < 8; nt++) {
            const int col = nb + wn0 + 8 * nt + 2 * tig;
            *reinterpret_cast<float2*>(ob + (size_t)row * N_DIM + col) =
                make_float2(acc[mt][nt][0], acc[mt][nt][1]);
            *reinterpret_cast<float2*>(ob + (size_t)(row + 8) * N_DIM + col) =
                make_float2(acc[mt][nt][2], acc[mt][nt][3]);
        }
    }
}

// ---------------- residual pass ----------------------------------------------
// out[b][m][n] += sum_j v_j * XhT[c_j][bn], deterministic per (m, bn).
__global__ void __launch_bounds__(128) residual_kernel(float* __restrict__ out) {
    const int m   = blockIdx.y;
    const int cnt = g_ResCnt[m];
    if (cnt == 0) return;
    const int bn = blockIdx.x * 512 + threadIdx.x * 4;
    const int b  = bn >> 11;
    const int n  = bn & (N_DIM - 1);
    float4 a = make_float4(0.f, 0.f, 0.f, 0.f);
    for (int j = 0; j < cnt; j++) {
        const float v = g_ResVal[(size_t)m * RESCAP + j];
        const int   c = g_ResCol[(size_t)m * RESCAP + j];
        const __half* xr = g_XhT + (size_t)c * BN_DIM + bn;
        const float2 f01 = __half22float2(*reinterpret_cast<const __half2*>(xr));
        const float2 f23 = __half22float2(*reinterpret_cast<const __half2*>(xr + 2));
        a.x += v * f01.x; a.y += v * f01.y;
        a.z += v * f23.x; a.w += v * f23.y;
    }
    float* op = out + ((size_t)b * M_DIM + m) * N_DIM + n;
    float4 cur = *reinterpret_cast<float4*>(op);
    cur.x += a.x; cur.y += a.y; cur.z += a.z; cur.w += a.w;
    *reinterpret_cast<float4*>(op) = cur;
}

// ---------------- host side --------------------------------------------------
extern "C" void kernel_launch(void* const* d_in, const int* in_sizes, int n_in,
                              void* d_out, int out_size) {
    const float* x           = (const float*)d_in[0];
    const float* values      = (const float*)d_in[1];
    const int*   row_offsets = (const int*)  d_in[2];
    const int*   col_indices = (const int*)  d_in[3];
    float*       out         = (float*)d_out;
    (void)in_sizes; (void)n_in; (void)out_size;

    const size_t wN = (size_t)M_DIM * K_DIM;
    const size_t xN = (size_t)BN_DIM * K_DIM;
    const size_t mpN = (size_t)NK32 * MT16 * 16;

    zero_wh_kernel<<<(unsigned)((wN / 8 + 255) / 256), 256>>>();
    scatter_kernel<<<M_DIM, 128>>>(values, row_offsets, col_indices);
    compress_kernel<<<M_DIM, 32>>>();
    repack_meta_kernel<<<(unsigned)((mpN + 255) / 256), 256>>>();
    convx_kernel<<<(unsigned)((xN / 4 + 255) / 256), 256>>>(x);
    txp_kernel<<<dim3(BN_DIM / 32, K_DIM / 32), dim3(32, 8)>>>(x);

    cudaFuncSetAttribute(gemm_kernel,
                         cudaFuncAttributeMaxDynamicSharedMemorySize, SMEM_TOTAL);
    gemm_kernel<<<dim3(M_DIM / BM, BN_DIM / BN), 128, SMEM_TOTAL>>>(out);
    residual_kernel<<<dim3(BN_DIM / 512, M_DIM), 128>>>(out);
}

// round 12
// speedup vs baseline: 1.2860x; 1.1444x over previous
#include <cuda_runtime.h>
#include <cuda_fp16.h>
#include <cstdint>

#define M_DIM 4096
#define K_DIM 4096
#define B_DIM 4
#define N_DIM 2048
#define BN_DIM (B_DIM * N_DIM)      // 8192

// GEMM tiling: CTA 128x128, 4 warps of 64x64, BK=64 (proven optimal; at the
// legacy-HMMA MAC-rate wall: ~157.5 dense MAC/cyc/SMSP)
#define BM 128
#define BN 128
#define BK 64
#define NSTAGE 3
#define PADK 72                      // pitch in halves (144 B): conflict-free ldmatrix
#define TRB (PADK * 2)               // tile row bytes = 144
#define A_TILE_BYTES (BM * TRB)      // 18432
#define B_TILE_BYTES (BN * TRB)      // 18432
#define STAGE_BYTES (A_TILE_BYTES + B_TILE_BYTES)   // 36864
#define SMEM_TOTAL (NSTAGE * STAGE_BYTES)           // 110592 -> 2 CTAs/SM
#define NKT (K_DIM / BK)             // 64

// ---------------- scratch ----------------------------------------------------
__device__ __align__(1024) __half g_Wh[(size_t)M_DIM * K_DIM];
__device__ __align__(1024) __half g_Xh[(size_t)BN_DIM * K_DIM];

// ---------------- helpers ----------------------------------------------------
__device__ __forceinline__ uint32_t smem_u32(const void* p) {
    uint32_t a;
    asm("{ .reg .u64 t; cvta.to.shared.u64 t, %1; cvt.u32.u64 %0, t; }" : "=r"(a) : "l"(p));
    return a;
}

#define CP16(dst_u32, src_ptr) \
    asm volatile("cp.async.cg.shared.global [%0], [%1], 16;" \
                 :: "r"(dst_u32), "l"(src_ptr) : "memory")
#define CP_COMMIT() asm volatile("cp.async.commit_group;" ::: "memory")
#define CP_WAIT(n)  asm volatile("cp.async.wait_group %0;" :: "n"(n) : "memory")

__device__ __forceinline__ void ldsm_x4(uint32_t* r, uint32_t addr) {
    asm volatile("ldmatrix.sync.aligned.m8n8.x4.shared.b16 {%0,%1,%2,%3}, [%4];"
        : "=r"(r[0]), "=r"(r[1]), "=r"(r[2]), "=r"(r[3]) : "r"(addr));
}

__device__ __forceinline__ void mma16816(float* d, const uint32_t* a, const uint32_t* b) {
    asm volatile(
        "mma.sync.aligned.m16n8k16.row.col.f32.f16.f16.f32 "
        "{%0,%1,%2,%3}, {%4,%5,%6,%7}, {%8,%9}, {%0,%1,%2,%3};"
        : "+f"(d[0]), "+f"(d[1]), "+f"(d[2]), "+f"(d[3])
        : "r"(a[0]), "r"(a[1]), "r"(a[2]), "r"(a[3]), "r"(b[0]), "r"(b[1]));
}

// ---------------- prep kernels -----------------------------------------------
// Fused zero + deterministic CSR scatter: build each dense fp16 W row in smem,
// write once coalesced.  Duplicate columns folded in fp32 (sorted runs).
__global__ void __launch_bounds__(128) buildw_kernel(
    const float* __restrict__ values, const int* __restrict__ row_offsets,
    const int* __restrict__ cols) {
    __shared__ __half row[K_DIM];                    // 8 KB
    const int m = blockIdx.x;

    uint4* r4 = reinterpret_cast<uint4*>(row);
    #pragma unroll
    for (int i = threadIdx.x; i < K_DIM / 8; i += 128)
        r4[i] = make_uint4(0u, 0u, 0u, 0u);
    __syncthreads();

    const int s = row_offsets[m], e = row_offsets[m + 1];
    for (int j = s + threadIdx.x; j < e; j += 128) {
        const int c = cols[j];
        if (j > s && cols[j - 1] == c) continue;     // not head of duplicate run
        float sum = values[j];
        int jj = j + 1;
        while (jj < e && cols[jj] == c) { sum += values[jj]; jj++; }
        row[c] = __float2half_rn(sum);
    }
    __syncthreads();

    uint4* dst = reinterpret_cast<uint4*>(g_Wh + (size_t)m * K_DIM);
    #pragma unroll
    for (int i = threadIdx.x; i < K_DIM / 8; i += 128)
        dst[i] = r4[i];
}

// fp32 -> fp16 conversion of X, 8 elems/thread, single 16B store.
__global__ void __launch_bounds__(256) convx_kernel(const float* __restrict__ x) {
    const size_t i = ((size_t)blockIdx.x * 256 + threadIdx.x) * 8;
    const float4 a = *reinterpret_cast<const float4*>(&x[i]);
    const float4 b = *reinterpret_cast<const float4*>(&x[i + 4]);
    __half2 h[4];
    h[0] = __halves2half2(__float2half_rn(a.x), __float2half_rn(a.y));
    h[1] = __halves2half2(__float2half_rn(a.z), __float2half_rn(a.w));
    h[2] = __halves2half2(__float2half_rn(b.x), __float2half_rn(b.y));
    h[3] = __halves2half2(__float2half_rn(b.z), __float2half_rn(b.w));
    *reinterpret_cast<uint4*>(&g_Xh[i]) = *reinterpret_cast<const uint4*>(h);
}

// ---------------- GEMM -------------------------------------------------------
// C[M, BN_DIM] = Wh * Xh^T, fp32 accumulate.  128 threads, warp grid 2x2,
// warp tile 64x64 (mt=4 m16 tiles, nt=8 n8 tiles).  2 CTAs/SM.
__global__ void __launch_bounds__(128, 2) gemm_kernel(float* __restrict__ out) {
    extern __shared__ char smem[];
    const int tid  = threadIdx.x;
    const int wid  = tid >> 5;
    const int lane = tid & 31;
    const int grp  = lane >> 2;
    const int tig  = lane & 3;
    const int wm0  = (wid & 1) * 64;
    const int wn0  = (wid >> 1) * 64;
    const int m0   = blockIdx.x * BM;
    const int bn0  = blockIdx.y * BN;

    const uint32_t sbase = smem_u32(smem);

    // ldmatrix lane-derived address components
    const int a_row_l = (lane & 7) + 8 * ((lane >> 3) & 1);
    const int a_kx    = 16 * ((lane >> 4) & 1);
    const int b_row_l = (lane & 7) + 8 * ((lane >> 4) & 1);
    const int b_kx    = 16 * ((lane >> 3) & 1);

    const __half* gA = g_Wh + (size_t)m0  * K_DIM;
    const __half* gB = g_Xh + (size_t)bn0 * K_DIM;

    // cp.async per stage: 1024 chunks A + 1024 chunks B (16 B each), 128 thr
    // -> 8 A + 8 B chunks per thread.  chunk c: row = c>>3, ch = c&7.
    #define LOAD_STAGE(stg, ktidx) do {                                         \
        const uint32_t sb_ = sbase + (stg) * STAGE_BYTES;                       \
        const int kh_ = (ktidx) * BK;                                           \
        _Pragma("unroll")                                                       \
        for (int i_ = 0; i_ < 8; i_++) {                                        \
            const int c_   = tid + i_ * 128;                                    \
            const int row_ = c_ >> 3, ch_ = c_ & 7;                             \
            const uint32_t d_ = sb_ + row_ * TRB + ch_ * 16;                    \
            const size_t  g_  = (size_t)row_ * K_DIM + kh_ + ch_ * 8;           \
            CP16(d_, gA + g_);                                                  \
            CP16(d_ + A_TILE_BYTES, gB + g_);                                   \
        }                                                                       \
    } while (0)

    #pragma unroll
    for (int s = 0; s < NSTAGE - 1; s++) { LOAD_STAGE(s, s); CP_COMMIT(); }

    float acc[4][8][4];
    #pragma unroll
    for (int mt = 0; mt < 4; mt++)
        #pragma unroll
        for (int nt = 0; nt < 8; nt++)
            #pragma unroll
            for (int r = 0; r < 4; r++) acc[mt][nt][r] = 0.f;

    for (int kt = 0; kt < NKT; kt++) {
        CP_WAIT(NSTAGE - 2);
        __syncthreads();
        if (kt + NSTAGE - 1 < NKT) LOAD_STAGE((kt + NSTAGE - 1) % NSTAGE, kt + NSTAGE - 1);
        CP_COMMIT();

        const uint32_t st = sbase + (kt % NSTAGE) * STAGE_BYTES;
        const uint32_t sA = st;
        const uint32_t sB = st + A_TILE_BYTES;

        #pragma unroll
        for (int ks = 0; ks < 4; ks++) {
            const int kb = ks * 32;
            uint32_t bf[8][2];
            #pragma unroll
            for (int ntp = 0; ntp < 4; ntp++) {
                uint32_t r[4];
                ldsm_x4(r, sB + (wn0 + 16 * ntp + b_row_l) * TRB + kb + b_kx);
                bf[2 * ntp][0]     = r[0];
                bf[2 * ntp][1]     = r[1];
                bf[2 * ntp + 1][0] = r[2];
                bf[2 * ntp + 1][1] = r[3];
            }
            uint32_t ah[4][4];
            #pragma unroll
            for (int mt = 0; mt < 4; mt++)
                ldsm_x4(ah[mt], sA + (wm0 + 16 * mt + a_row_l) * TRB + kb + a_kx);
            #pragma unroll
            for (int mt = 0; mt < 4; mt++)
                #pragma unroll
                for (int nt = 0; nt < 8; nt++)
                    mma16816(acc[mt][nt], ah[mt], bf[nt]);
        }
    }

    // epilogue
    const int b  = bn0 >> 11;               // / N_DIM
    const int nb = bn0 & (N_DIM - 1);
    float* ob = out + (size_t)b * M_DIM * N_DIM;
    #pragma unroll
    for (int mt = 0; mt < 4; mt++) {
        const int row = m0 + wm0 + 16 * mt + grp;
        #pragma unroll
        for (int nt = 0; nt < 8; nt++) {
            const int col = nb + wn0 + 8 * nt + 2 * tig;
            *reinterpret_cast<float2*>(ob + (size_t)row * N_DIM + col) =
                make_float2(acc[mt][nt][0], acc[mt][nt][1]);
            *reinterpret_cast<float2*>(ob + (size_t)(row + 8) * N_DIM + col) =
                make_float2(acc[mt][nt][2], acc[mt][nt][3]);
        }
    }
}

// ---------------- host side --------------------------------------------------
extern "C" void kernel_launch(void* const* d_in, const int* in_sizes, int n_in,
                              void* d_out, int out_size) {
    const float* x           = (const float*)d_in[0];  // [B, N, K] == [BN, K]
    const float* values      = (const float*)d_in[1];
    const int*   row_offsets = (const int*)  d_in[2];
    const int*   col_indices = (const int*)  d_in[3];
    float*       out         = (float*)d_out;
    (void)in_sizes; (void)n_in; (void)out_size;

    const size_t xN = (size_t)BN_DIM * K_DIM;  // 33.5M halves

    buildw_kernel<<<M_DIM, 128>>>(values, row_offsets, col_indices);
    convx_kernel<<<(unsigned)(xN / 8 / 256), 256>>>(x);

    cudaFuncSetAttribute(gemm_kernel,
                         cudaFuncAttributeMaxDynamicSharedMemorySize, SMEM_TOTAL);
    gemm_kernel<<<dim3(M_DIM / BM, BN_DIM / BN), 128, SMEM_TOTAL>>>(out);
}

// round 13
// speedup vs baseline: 1.3114x; 1.0197x over previous
#include <cuda_runtime.h>
#include <cuda_fp16.h>
#include <cstdint>

#define M_DIM 4096
#define K_DIM 4096
#define B_DIM 4
#define N_DIM 2048
#define BN_DIM (B_DIM * N_DIM)      // 8192

// GEMM tiling: CTA 128x128, 4 warps of 64x64, BK=64 (at the legacy-HMMA
// MAC-rate wall: ~157.5 dense MAC/cyc/SMSP)
#define BM 128
#define BN 128
#define BK 64
#define NSTAGE 3
#define PADK 72                      // pitch in halves (144 B): conflict-free ldmatrix
#define TRB (PADK * 2)               // tile row bytes = 144
#define A_TILE_BYTES (BM * TRB)      // 18432
#define B_TILE_BYTES (BN * TRB)      // 18432
#define STAGE_BYTES (A_TILE_BYTES + B_TILE_BYTES)   // 36864
#define SMEM_TOTAL (NSTAGE * STAGE_BYTES)           // 110592 -> 2 CTAs/SM
#define NKT (K_DIM / BK)             // 64

// ---------------- scratch ----------------------------------------------------
__device__ __align__(1024) __half g_Wh[(size_t)M_DIM * K_DIM];
__device__ __align__(1024) __half g_Xh[(size_t)BN_DIM * K_DIM];

// ---------------- helpers ----------------------------------------------------
__device__ __forceinline__ uint32_t smem_u32(const void* p) {
    uint32_t a;
    asm("{ .reg .u64 t; cvta.to.shared.u64 t, %1; cvt.u32.u64 %0, t; }" : "=r"(a) : "l"(p));
    return a;
}

#define CP16(dst_u32, src_ptr) \
    asm volatile("cp.async.cg.shared.global [%0], [%1], 16;" \
                 :: "r"(dst_u32), "l"(src_ptr) : "memory")
#define CP_COMMIT() asm volatile("cp.async.commit_group;" ::: "memory")
#define CP_WAIT(n)  asm volatile("cp.async.wait_group %0;" :: "n"(n) : "memory")

__device__ __forceinline__ void ldsm_x4(uint32_t* r, uint32_t addr) {
    asm volatile("ldmatrix.sync.aligned.m8n8.x4.shared.b16 {%0,%1,%2,%3}, [%4];"
        : "=r"(r[0]), "=r"(r[1]), "=r"(r[2]), "=r"(r[3]) : "r"(addr));
}

__device__ __forceinline__ void mma16816(float* d, const uint32_t* a, const uint32_t* b) {
    asm volatile(
        "mma.sync.aligned.m16n8k16.row.col.f32.f16.f16.f32 "
        "{%0,%1,%2,%3}, {%4,%5,%6,%7}, {%8,%9}, {%0,%1,%2,%3};"
        : "+f"(d[0]), "+f"(d[1]), "+f"(d[2]), "+f"(d[3])
        : "r"(a[0]), "r"(a[1]), "r"(a[2]), "r"(a[3]), "r"(b[0]), "r"(b[1]));
}

// ---------------- prep kernels -----------------------------------------------
// Fused zero + deterministic CSR scatter: build each dense fp16 W row in smem,
// write once coalesced.  Duplicate columns folded in fp32 (sorted runs).
__global__ void __launch_bounds__(128) buildw_kernel(
    const float* __restrict__ values, const int* __restrict__ row_offsets,
    const int* __restrict__ cols) {
    __shared__ __half row[K_DIM];                    // 8 KB
    const int m = blockIdx.x;

    uint4* r4 = reinterpret_cast<uint4*>(row);
    #pragma unroll
    for (int i = threadIdx.x; i < K_DIM / 8; i += 128)
        r4[i] = make_uint4(0u, 0u, 0u, 0u);
    __syncthreads();

    const int s = row_offsets[m], e = row_offsets[m + 1];
    for (int j = s + threadIdx.x; j < e; j += 128) {
        const int c = cols[j];
        if (j > s && cols[j - 1] == c) continue;     // not head of duplicate run
        float sum = values[j];
        int jj = j + 1;
        while (jj < e && cols[jj] == c) { sum += values[jj]; jj++; }
        row[c] = __float2half_rn(sum);
    }
    __syncthreads();

    uint4* dst = reinterpret_cast<uint4*>(g_Wh + (size_t)m * K_DIM);
    #pragma unroll
    for (int i = threadIdx.x; i < K_DIM / 8; i += 128)
        dst[i] = r4[i];
}

// fp32 -> fp16 conversion of a range of X, 8 elems/thread, single 16B store.
__global__ void __launch_bounds__(256) convx_kernel(const float* __restrict__ x,
                                                    size_t base) {
    const size_t i = base + ((size_t)blockIdx.x * 256 + threadIdx.x) * 8;
    const float4 a = *reinterpret_cast<const float4*>(&x[i]);
    const float4 b = *reinterpret_cast<const float4*>(&x[i + 4]);
    __half2 h[4];
    h[0] = __halves2half2(__float2half_rn(a.x), __float2half_rn(a.y));
    h[1] = __halves2half2(__float2half_rn(a.z), __float2half_rn(a.w));
    h[2] = __halves2half2(__float2half_rn(b.x), __float2half_rn(b.y));
    h[3] = __halves2half2(__float2half_rn(b.z), __float2half_rn(b.w));
    *reinterpret_cast<uint4*>(&g_Xh[i]) = *reinterpret_cast<const uint4*>(h);
}

// ---------------- GEMM -------------------------------------------------------
// C[M, bn_base:bn_base+32*BN] = Wh * Xh^T slice, fp32 accumulate.
// 128 threads, warp grid 2x2, warp tile 64x64.  2 CTAs/SM.
__global__ void __launch_bounds__(128, 2) gemm_kernel(float* __restrict__ out,
                                                      int bn_base) {
    extern __shared__ char smem[];
    const int tid  = threadIdx.x;
    const int wid  = tid >> 5;
    const int lane = tid & 31;
    const int grp  = lane >> 2;
    const int tig  = lane & 3;
    const int wm0  = (wid & 1) * 64;
    const int wn0  = (wid >> 1) * 64;
    const int m0   = blockIdx.x * BM;
    const int bn0  = bn_base + blockIdx.y * BN;

    const uint32_t sbase = smem_u32(smem);

    // ldmatrix lane-derived address components
    const int a_row_l = (lane & 7) + 8 * ((lane >> 3) & 1);
    const int a_kx    = 16 * ((lane >> 4) & 1);
    const int b_row_l = (lane & 7) + 8 * ((lane >> 4) & 1);
    const int b_kx    = 16 * ((lane >> 3) & 1);

    const __half* gA = g_Wh + (size_t)m0  * K_DIM;
    const __half* gB = g_Xh + (size_t)bn0 * K_DIM;

    // cp.async per stage: 1024 chunks A + 1024 chunks B (16 B each), 128 thr
    // -> 8 A + 8 B chunks per thread.  chunk c: row = c>>3, ch = c&7.
    #define LOAD_STAGE(stg, ktidx) do {                                         \
        const uint32_t sb_ = sbase + (stg) * STAGE_BYTES;                       \
        const int kh_ = (ktidx) * BK;                                           \
        _Pragma("unroll")                                                       \
        for (int i_ = 0; i_ < 8; i_++) {                                        \
            const int c_   = tid + i_ * 128;                                    \
            const int row_ = c_ >> 3, ch_ = c_ & 7;                             \
            const uint32_t d_ = sb_ + row_ * TRB + ch_ * 16;                    \
            const size_t  g_  = (size_t)row_ * K_DIM + kh_ + ch_ * 8;           \
            CP16(d_, gA + g_);                                                  \
            CP16(d_ + A_TILE_BYTES, gB + g_);                                   \
        }                                                                       \
    } while (0)

    #pragma unroll
    for (int s = 0; s < NSTAGE - 1; s++) { LOAD_STAGE(s, s); CP_COMMIT(); }

    float acc[4][8][4];
    #pragma unroll
    for (int mt = 0; mt < 4; mt++)
        #pragma unroll
        for (int nt = 0; nt < 8; nt++)
            #pragma unroll
            for (int r = 0; r < 4; r++) acc[mt][nt][r] = 0.f;

    for (int kt = 0; kt < NKT; kt++) {
        CP_WAIT(NSTAGE - 2);
        __syncthreads();
        if (kt + NSTAGE - 1 < NKT) LOAD_STAGE((kt + NSTAGE - 1) % NSTAGE, kt + NSTAGE - 1);
        CP_COMMIT();

        const uint32_t st = sbase + (kt % NSTAGE) * STAGE_BYTES;
        const uint32_t sA = st;
        const uint32_t sB = st + A_TILE_BYTES;

        #pragma unroll
        for (int ks = 0; ks < 4; ks++) {
            const int kb = ks * 32;
            uint32_t bf[8][2];
            #pragma unroll
            for (int ntp = 0; ntp < 4; ntp++) {
                uint32_t r[4];
                ldsm_x4(r, sB + (wn0 + 16 * ntp + b_row_l) * TRB + kb + b_kx);
                bf[2 * ntp][0]     = r[0];
                bf[2 * ntp][1]     = r[1];
                bf[2 * ntp + 1][0] = r[2];
                bf[2 * ntp + 1][1] = r[3];
            }
            uint32_t ah[4][4];
            #pragma unroll
            for (int mt = 0; mt < 4; mt++)
                ldsm_x4(ah[mt], sA + (wm0 + 16 * mt + a_row_l) * TRB + kb + a_kx);
            #pragma unroll
            for (int mt = 0; mt < 4; mt++)
                #pragma unroll
                for (int nt = 0; nt < 8; nt++)
                    mma16816(acc[mt][nt], ah[mt], bf[nt]);
        }
    }

    // epilogue
    const int b  = bn0 >> 11;               // / N_DIM
    const int nb = bn0 & (N_DIM - 1);
    float* ob = out + (size_t)b * M_DIM * N_DIM;
    #pragma unroll
    for (int mt = 0; mt < 4; mt++) {
        const int row = m0 + wm0 + 16 * mt + grp;
        #pragma unroll
        for (int nt = 0; nt < 8; nt++) {
            const int col = nb + wn0 + 8 * nt + 2 * tig;
            *reinterpret_cast<float2*>(ob + (size_t)row * N_DIM + col) =
                make_float2(acc[mt][nt][0], acc[mt][nt][1]);
            *reinterpret_cast<float2*>(ob + (size_t)(row + 8) * N_DIM + col) =
                make_float2(acc[mt][nt][2], acc[mt][nt][3]);
        }
    }
}

// ---------------- host side --------------------------------------------------
extern "C" void kernel_launch(void* const* d_in, const int* in_sizes, int n_in,
                              void* d_out, int out_size) {
    const float* x           = (const float*)d_in[0];  // [B, N, K] == [BN, K]
    const float* values      = (const float*)d_in[1];
    const int*   row_offsets = (const int*)  d_in[2];
    const int*   col_indices = (const int*)  d_in[3];
    float*       out         = (float*)d_out;
    (void)in_sizes; (void)n_in; (void)out_size;

    static bool inited = false;
    static cudaStream_t sW, sG;
    static cudaEvent_t evFork, evW, evX0, evG0;
    if (!inited) {
        cudaStreamCreateWithFlags(&sW, cudaStreamNonBlocking);
        cudaStreamCreateWithFlags(&sG, cudaStreamNonBlocking);
        cudaEventCreateWithFlags(&evFork, cudaEventDisableTiming);
        cudaEventCreateWithFlags(&evW,    cudaEventDisableTiming);
        cudaEventCreateWithFlags(&evX0,   cudaEventDisableTiming);
        cudaEventCreateWithFlags(&evG0,   cudaEventDisableTiming);
        cudaFuncSetAttribute(gemm_kernel,
                             cudaFuncAttributeMaxDynamicSharedMemorySize, SMEM_TOTAL);
        inited = true;
    }

    const size_t xN   = (size_t)BN_DIM * K_DIM;   // 33.5M halves
    const size_t half = xN / 2;
    const unsigned cblk = (unsigned)(half / 8 / 256);

    // fork sW from the (captured) main stream
    cudaEventRecord(evFork, 0);
    cudaStreamWaitEvent(sW, evFork, 0);

    // W build on sW, X conversion chunks on the main stream
    buildw_kernel<<<M_DIM, 128, 0, sW>>>(values, row_offsets, col_indices);
    cudaEventRecord(evW, sW);

    convx_kernel<<<cblk, 256>>>(x, 0);
    cudaEventRecord(evX0, 0);
    convx_kernel<<<cblk, 256>>>(x, half);

    // gemm half 0 on sG: needs W + X[0:half)
    cudaStreamWaitEvent(sG, evW, 0);
    cudaStreamWaitEvent(sG, evX0, 0);
    gemm_kernel<<<dim3(M_DIM / BM, BN_DIM / BN / 2), 128, SMEM_TOTAL, sG>>>(out, 0);
    cudaEventRecord(evG0, sG);

    // gemm half 1 on main stream: needs W + X[half:) (implicit on this stream)
    cudaStreamWaitEvent(0, evW, 0);
    gemm_kernel<<<dim3(M_DIM / BM, BN_DIM / BN / 2), 128, SMEM_TOTAL>>>(out, BN_DIM / 2);

    // join
    cudaStreamWaitEvent(0, evG0, 0);
}